// round 1
// baseline (speedup 1.0000x reference)
#include <cuda_runtime.h>
#include <math.h>

#define NN 10000
#define EE 160000
#define MULQ 16
#define WNQ 1024
#define TE 16
#define NHALF 512
#define THREADS 256

// shared memory layout (float offsets)
#define OFF_W2   0          // 64*512
#define OFF_W    32768      // 16*512
#define OFF_H    40960      // 64*16
#define OFF_W1   41984      // 16*64
#define OFF_B1   43008      // 64
#define OFF_B2   43072      // 512
#define OFF_EMB  43584      // 16*16
#define OFF_X    43840      // 16*64
#define OFF_SH   44864      // 16*4
#define OFF_SRC  44928      // 16 ints
#define OFF_DST  44944      // 16 ints
#define SMEM_FLOATS 44960
#define SMEM_BYTES (SMEM_FLOATS * 4)

__device__ float g_agg[NN * 64];

static __device__ __forceinline__ unsigned long long pack_dup(float x) {
    unsigned long long r;
    asm("mov.b64 %0, {%1, %1};" : "=l"(r) : "f"(x));
    return r;
}
static __device__ __forceinline__ float2 unpack2(unsigned long long v) {
    float2 f;
    asm("mov.b64 {%0, %1}, %2;" : "=f"(f.x), "=f"(f.y) : "l"(v));
    return f;
}
#define FMA2(acc, a, b) asm("fma.rn.f32x2 %0, %1, %2, %0;" : "+l"(acc) : "l"(a), "l"(b))

__global__ void zero_kernel() {
    g_agg[blockIdx.x * 1024 + threadIdx.x] = 0.0f;
}

__global__ __launch_bounds__(THREADS, 1)
void edge_kernel(const float* __restrict__ nf,
                 const float* __restrict__ esh,
                 const float* __restrict__ emb,
                 const float* __restrict__ w1,
                 const float* __restrict__ b1,
                 const float* __restrict__ w2,
                 const float* __restrict__ b2,
                 const int*   __restrict__ eidx)
{
    extern __shared__ float sm[];
    float* sW2  = sm + OFF_W2;
    float* sW   = sm + OFF_W;
    float* sH   = sm + OFF_H;
    float* sW1  = sm + OFF_W1;
    float* sB1  = sm + OFF_B1;
    float* sB2  = sm + OFF_B2;
    float* sEmb = sm + OFF_EMB;
    float* sX   = sm + OFF_X;
    float* sSH  = sm + OFF_SH;
    int*   sSrc = (int*)(sm + OFF_SRC);
    int*   sDst = (int*)(sm + OFF_DST);

    const int t = threadIdx.x;
    const int role = blockIdx.x & 1;
    const int colbase = role * NHALF;

    // one-time per-block staging: w2 half, w1, b1, b2 half
    for (int i = t; i < 64 * NHALF; i += THREADS) {
        int k = i >> 9, n = i & 511;
        sW2[i] = w2[k * WNQ + colbase + n];
    }
    for (int i = t; i < 16 * 64; i += THREADS) sW1[i] = w1[i];
    if (t < 64) sB1[t] = b1[t];
    for (int i = t; i < NHALF; i += THREADS) sB2[i] = b2[colbase + i];
    __syncthreads();

    const float ALPHA = 0.17677669529663687f;   // 1/sqrt(2*MUL)
    const float INV3  = 0.5773502691896258f;    // 1/sqrt(3)

    const int nblocks_role = gridDim.x >> 1;
    for (int tile = blockIdx.x >> 1; tile < EE / TE; tile += nblocks_role) {
        const int e0 = tile * TE;

        // ---- phase 0: stage edge meta ----
        if (t < 16)       sSrc[t]      = eidx[e0 + t];
        else if (t < 32)  sDst[t - 16] = eidx[EE + e0 + (t - 16)];
        else if (t < 96)  { int q = t - 32; sSH[q] = esh[e0 * 4 + q]; }
        { sEmb[t] = emb[e0 * 16 + t]; }   // 256 contiguous floats
        __syncthreads();

        // ---- phase 1: contraction vectors + hidden h ----
        {
            int e = t >> 4, u = t & 15;
            int src = sSrc[e];
            float shs = sSH[e * 4];
            if (role == 0) {
                float x = nf[src * 64 + u];
                sX[e * 64 + u]      = x;         // xs  (for y01)
                sX[e * 64 + 16 + u] = shs * x;   // a   (for y00)
            } else {
                float sh1 = sSH[e*4+1], sh2 = sSH[e*4+2], sh3 = sSH[e*4+3];
                float xv0 = nf[src*64 + 16 + u*3 + 0];
                float xv1 = nf[src*64 + 16 + u*3 + 1];
                float xv2 = nf[src*64 + 16 + u*3 + 2];
                sX[e*64 + u]      = sh1*xv0 + sh2*xv1 + sh3*xv2; // b (for y11)
                sX[e*64 + 16 + u] = shs * xv0;                   // for y10 i=0
                sX[e*64 + 32 + u] = shs * xv1;                   // i=1
                sX[e*64 + 48 + u] = shs * xv2;                   // i=2
            }
        }
        #pragma unroll
        for (int r = 0; r < 4; ++r) {
            int task = t + r * THREADS;          // 1024 = 16 edges * 64 hidden
            int e = task & 15, j = task >> 4;
            float acc = sB1[j];
            #pragma unroll
            for (int k = 0; k < 16; ++k) acc += sEmb[e * 16 + k] * sW1[k * 64 + j];
            sH[j * 16 + e] = acc / (1.0f + __expf(-acc));   // silu
        }
        __syncthreads();

        // ---- phase 2: GEMM  W[16 x 512] = H[16 x 64] @ w2half[64 x 512] ----
        unsigned long long acc[4][4];
        #pragma unroll
        for (int i = 0; i < 4; ++i)
            #pragma unroll
            for (int j = 0; j < 4; ++j) acc[i][j] = 0ull;

        const int mg4 = (t >> 6) << 2;   // edge base (0,4,8,12)
        const int nb  = (t & 63) << 3;   // col base (0..504 step 8)
        #pragma unroll 8
        for (int k = 0; k < 64; ++k) {
            float4 a4 = *reinterpret_cast<const float4*>(sH + k * 16 + mg4);
            const float* wr = sW2 + k * NHALF + nb;
            ulonglong2 bA = *reinterpret_cast<const ulonglong2*>(wr);
            ulonglong2 bB = *reinterpret_cast<const ulonglong2*>(wr + 4);
            unsigned long long am;
            am = pack_dup(a4.x);
            FMA2(acc[0][0], am, bA.x); FMA2(acc[0][1], am, bA.y);
            FMA2(acc[0][2], am, bB.x); FMA2(acc[0][3], am, bB.y);
            am = pack_dup(a4.y);
            FMA2(acc[1][0], am, bA.x); FMA2(acc[1][1], am, bA.y);
            FMA2(acc[1][2], am, bB.x); FMA2(acc[1][3], am, bB.y);
            am = pack_dup(a4.z);
            FMA2(acc[2][0], am, bA.x); FMA2(acc[2][1], am, bA.y);
            FMA2(acc[2][2], am, bB.x); FMA2(acc[2][3], am, bB.y);
            am = pack_dup(a4.w);
            FMA2(acc[3][0], am, bA.x); FMA2(acc[3][1], am, bA.y);
            FMA2(acc[3][2], am, bB.x); FMA2(acc[3][3], am, bB.y);
        }
        #pragma unroll
        for (int mi = 0; mi < 4; ++mi)
            #pragma unroll
            for (int j = 0; j < 4; ++j) {
                float2 f = unpack2(acc[mi][j]);
                int n0 = nb + 2 * j;
                sW[(mg4 + mi) * NHALF + n0]     = f.x + sB2[n0];
                sW[(mg4 + mi) * NHALF + n0 + 1] = f.y + sB2[n0 + 1];
            }
        __syncthreads();

        // ---- phase 3: contractions + atomic scatter ----
        if (role == 0) {
            #pragma unroll
            for (int r = 0; r < 2; ++r) {
                int task = t + r * THREADS;       // 512 = 16 edges * 32 outputs
                int e = task >> 5, o = task & 31;
                int v = o & 15, sel = o >> 4;     // sel0: y00 (a), sel1: y01 (xs)
                const float* x = sX + e * 64 + (sel ? 0 : 16);
                const float* w = sW + e * NHALF + (sel ? 256 : 0) + v;
                float y = 0.0f;
                #pragma unroll
                for (int u = 0; u < 16; ++u) y += x[u] * w[u * 16];
                int dst = sDst[e];
                if (sel == 0) {
                    atomicAdd(&g_agg[dst * 64 + v], ALPHA * y);
                } else {
                    float ay = ALPHA * y;
                    atomicAdd(&g_agg[dst*64 + 16 + v*3 + 0], ay * sSH[e*4+1]);
                    atomicAdd(&g_agg[dst*64 + 16 + v*3 + 1], ay * sSH[e*4+2]);
                    atomicAdd(&g_agg[dst*64 + 16 + v*3 + 2], ay * sSH[e*4+3]);
                }
            }
        } else {
            #pragma unroll
            for (int r = 0; r < 4; ++r) {
                int task = t + r * THREADS;       // 1024 = 16 edges * 64 outputs
                int e = task >> 6, o = task & 63;
                int dst = sDst[e];
                if (o < 16) {                     // y11 with b -> msg_s part
                    int v = o;
                    const float* x = sX + e * 64;
                    const float* w = sW + e * NHALF + 256 + v;   // W11 local cols
                    float y = 0.0f;
                    #pragma unroll
                    for (int u = 0; u < 16; ++u) y += x[u] * w[u * 16];
                    atomicAdd(&g_agg[dst * 64 + v], ALPHA * INV3 * y);
                } else {                          // y10_i with shs*xv_i -> msg_v part
                    int oo = o - 16;
                    int i = oo >> 4, v = oo & 15;
                    const float* x = sX + e * 64 + 16 + i * 16;
                    const float* w = sW + e * NHALF + v;         // W10 local cols
                    float y = 0.0f;
                    #pragma unroll
                    for (int u = 0; u < 16; ++u) y += x[u] * w[u * 16];
                    atomicAdd(&g_agg[dst * 64 + 16 + v * 3 + i], ALPHA * y);
                }
            }
        }
        __syncthreads();
    }
}

__global__ __launch_bounds__(256)
void node_kernel(const float* __restrict__ nf,
                 const float* __restrict__ lw0,
                 const float* __restrict__ lw1,
                 float* __restrict__ out)
{
    __shared__ float sw0[256], sw1[256];
    int t = threadIdx.x;
    sw0[t] = lw0[t];
    sw1[t] = lw1[t];
    __syncthreads();

    int node = blockIdx.x * 16 + (t >> 4);
    int v = t & 15;
    const float* a = g_agg + node * 64;

    float ts = 0.0f, t0 = 0.0f, t1 = 0.0f, t2 = 0.0f;
    #pragma unroll
    for (int u = 0; u < 16; ++u) {
        float c0 = sw0[u * 16 + v];
        float c1 = sw1[u * 16 + v];
        ts += a[u] * c0;
        t0 += a[16 + u * 3 + 0] * c1;
        t1 += a[16 + u * 3 + 1] * c1;
        t2 += a[16 + u * 3 + 2] * c1;
    }
    const float S = 0.25f, EPS = 1e-8f;   // S = 1/sqrt(MUL)
    ts *= S; t0 *= S; t1 *= S; t2 *= S;

    float ns = fabsf(ts);
    float gs = ns / ((ns + EPS) * (1.0f + __expf(-ns)));   // silu(ns)/(ns+eps)
    float nv = sqrtf(t0 * t0 + t1 * t1 + t2 * t2);
    float gv = nv / ((nv + EPS) * (1.0f + __expf(-nv)));

    int base = node * 64;
    out[base + v] = nf[base + v] + ts * gs;
    out[base + 16 + v * 3 + 0] = nf[base + 16 + v * 3 + 0] + t0 * gv;
    out[base + 16 + v * 3 + 1] = nf[base + 16 + v * 3 + 1] + t1 * gv;
    out[base + 16 + v * 3 + 2] = nf[base + 16 + v * 3 + 2] + t2 * gv;
}

extern "C" void kernel_launch(void* const* d_in, const int* in_sizes, int n_in,
                              void* d_out, int out_size)
{
    const float* nf   = (const float*)d_in[0];
    const float* esh  = (const float*)d_in[1];
    const float* emb  = (const float*)d_in[2];
    const float* w1   = (const float*)d_in[3];
    const float* b1   = (const float*)d_in[4];
    const float* w2   = (const float*)d_in[5];
    const float* b2   = (const float*)d_in[6];
    const float* lw0  = (const float*)d_in[7];
    const float* lw1  = (const float*)d_in[8];
    const int*   eidx = (const int*)d_in[9];
    float* out = (float*)d_out;

    cudaFuncSetAttribute(edge_kernel, cudaFuncAttributeMaxDynamicSharedMemorySize, SMEM_BYTES);

    zero_kernel<<<625, 1024>>>();
    edge_kernel<<<152, THREADS, SMEM_BYTES>>>(nf, esh, emb, w1, b1, w2, b2, eidx);
    node_kernel<<<625, 256>>>(nf, lw0, lw1, out);
}

// round 2
// speedup vs baseline: 1.4434x; 1.4434x over previous
#include <cuda_runtime.h>
#include <math.h>

#define NN 10000
#define EE 160000
#define TE 32
#define NHALF 512
#define THREADS 512

// shared memory layout (float offsets)
#define OFF_W2   0          // 64*512
#define OFF_W    32768      // 32*512
#define OFF_H    49152      // 2048 u64 (64 k x 32 e, duplicated pairs)
#define OFF_W1   53248      // 16*64
#define OFF_B1   54272      // 64
#define OFF_B2   54336      // 512
#define OFF_EMB  54848      // 16*32 transposed [k][e]
#define OFF_X    55360      // 32*64
#define OFF_SH   57408      // 32*4
#define OFF_SRC  57536      // 32 ints
#define OFF_DST  57568      // 32 ints
#define SMEM_FLOATS 57600
#define SMEM_BYTES (SMEM_FLOATS * 4)   // 230400 <= 232448 opt-in max

__device__ float g_agg[NN * 64];

static __device__ __forceinline__ unsigned long long pack_dup(float x) {
    unsigned long long r;
    asm("mov.b64 %0, {%1, %1};" : "=l"(r) : "f"(x));
    return r;
}
static __device__ __forceinline__ float2 unpack2(unsigned long long v) {
    float2 f;
    asm("mov.b64 {%0, %1}, %2;" : "=f"(f.x), "=f"(f.y) : "l"(v));
    return f;
}
#define FMA2(acc, a, b) asm("fma.rn.f32x2 %0, %1, %2, %0;" : "+l"(acc) : "l"(a), "l"(b))

__global__ void zero_kernel() {
    g_agg[blockIdx.x * 1024 + threadIdx.x] = 0.0f;
}

__global__ __launch_bounds__(THREADS, 1)
void edge_kernel(const float* __restrict__ nf,
                 const float* __restrict__ esh,
                 const float* __restrict__ emb,
                 const float* __restrict__ w1,
                 const float* __restrict__ b1,
                 const float* __restrict__ w2,
                 const float* __restrict__ b2,
                 const int*   __restrict__ eidx)
{
    extern __shared__ float sm[];
    float* sW2  = sm + OFF_W2;
    float* sW   = sm + OFF_W;
    unsigned long long* sHd = (unsigned long long*)(sm + OFF_H);
    float* sW1  = sm + OFF_W1;
    float* sB1  = sm + OFF_B1;
    float* sB2  = sm + OFF_B2;
    float* sEmbT= sm + OFF_EMB;
    float* sX   = sm + OFF_X;
    float* sSH  = sm + OFF_SH;
    int*   sSrc = (int*)(sm + OFF_SRC);
    int*   sDst = (int*)(sm + OFF_DST);

    const int t = threadIdx.x;
    const int role = blockIdx.x & 1;
    const int colbase = role * NHALF;

    // one-time staging: w2 half, w1, b1, b2 half
    #pragma unroll
    for (int r = 0; r < 64; ++r) {
        int i = t + r * THREADS;
        int k = i >> 9, n = i & 511;
        sW2[i] = w2[k * 1024 + colbase + n];
    }
    for (int i = t; i < 16 * 64; i += THREADS) sW1[i] = w1[i];
    if (t < 64) sB1[t] = b1[t];
    if (t < NHALF) sB2[t] = b2[colbase + t];
    __syncthreads();

    const float ALPHA = 0.17677669529663687f;   // 1/sqrt(2*MUL)
    const float INV3  = 0.5773502691896258f;    // 1/sqrt(3)

    // GEMM thread tile mapping
    const int mg4 = (t >> 6) << 2;      // edge rows 0..28 step 4
    const int cg  = t & 63;
    const int nbA = cg << 2;            // cols 0..252
    const int nbB = nbA + 256;          // cols 256..508

    const int nrole = gridDim.x >> 1;
    for (int tile = blockIdx.x >> 1; tile < EE / TE; tile += nrole) {
        const int e0 = tile * TE;

        // ---- phase 0: stage edge meta ----
        if (t < 32)       sSrc[t]      = eidx[e0 + t];
        else if (t < 64)  sDst[t - 32] = eidx[EE + e0 + (t - 32)];
        else if (t < 192) sSH[t - 64]  = esh[e0 * 4 + (t - 64)];
        // transposed emb: sEmbT[k*32+e]
        {
            int k = t >> 5, e = t & 31;
            sEmbT[k * 32 + e] = emb[(e0 + e) * 16 + k];
        }
        __syncthreads();

        // ---- phase 1: contraction vectors + hidden h (duplicated pairs) ----
        {
            int e = t >> 4, u = t & 15;
            int src = sSrc[e];
            float shs = sSH[e * 4];
            if (role == 0) {
                float x = nf[src * 64 + u];
                sX[e * 64 + u]      = x;         // xs  (for y01)
                sX[e * 64 + 16 + u] = shs * x;   // a   (for y00)
            } else {
                float sh1 = sSH[e*4+1], sh2 = sSH[e*4+2], sh3 = sSH[e*4+3];
                float xv0 = nf[src*64 + 16 + u*3 + 0];
                float xv1 = nf[src*64 + 16 + u*3 + 1];
                float xv2 = nf[src*64 + 16 + u*3 + 2];
                sX[e*64 + u]      = sh1*xv0 + sh2*xv1 + sh3*xv2; // b (for y11)
                sX[e*64 + 16 + u] = shs * xv0;                   // y10 i=0
                sX[e*64 + 32 + u] = shs * xv1;                   // i=1
                sX[e*64 + 48 + u] = shs * xv2;                   // i=2
            }
        }
        #pragma unroll
        for (int r = 0; r < 4; ++r) {
            int task = t + r * THREADS;          // 2048 = 32 e * 64 hidden
            int e = task & 31, j = task >> 5;    // j warp-uniform, e lane-linear
            float acc = sB1[j];
            #pragma unroll
            for (int k = 0; k < 16; ++k) acc += sEmbT[k * 32 + e] * sW1[k * 64 + j];
            float h = acc / (1.0f + __expf(-acc));   // silu
            sHd[j * 32 + e] = pack_dup(h);
        }
        __syncthreads();

        // ---- phase 2: GEMM  W[32 x 512] = H[32 x 64] @ w2half[64 x 512] ----
        unsigned long long acc[4][4];
        #pragma unroll
        for (int i = 0; i < 4; ++i)
            #pragma unroll
            for (int j = 0; j < 4; ++j) acc[i][j] = 0ull;

        #pragma unroll 8
        for (int k = 0; k < 64; ++k) {
            ulonglong2 a01 = *reinterpret_cast<const ulonglong2*>(sHd + k * 32 + mg4);
            ulonglong2 a23 = *reinterpret_cast<const ulonglong2*>(sHd + k * 32 + mg4 + 2);
            const float* wr = sW2 + k * NHALF;
            ulonglong2 bA = *reinterpret_cast<const ulonglong2*>(wr + nbA);
            ulonglong2 bB = *reinterpret_cast<const ulonglong2*>(wr + nbB);
            FMA2(acc[0][0], a01.x, bA.x); FMA2(acc[0][1], a01.x, bA.y);
            FMA2(acc[0][2], a01.x, bB.x); FMA2(acc[0][3], a01.x, bB.y);
            FMA2(acc[1][0], a01.y, bA.x); FMA2(acc[1][1], a01.y, bA.y);
            FMA2(acc[1][2], a01.y, bB.x); FMA2(acc[1][3], a01.y, bB.y);
            FMA2(acc[2][0], a23.x, bA.x); FMA2(acc[2][1], a23.x, bA.y);
            FMA2(acc[2][2], a23.x, bB.x); FMA2(acc[2][3], a23.x, bB.y);
            FMA2(acc[3][0], a23.y, bA.x); FMA2(acc[3][1], a23.y, bA.y);
            FMA2(acc[3][2], a23.y, bB.x); FMA2(acc[3][3], a23.y, bB.y);
        }
        // epilogue: +bias, store; upper-half cols stored XOR-16 swizzled
        #pragma unroll
        for (int r = 0; r < 4; ++r) {
            float2 f0 = unpack2(acc[r][0]);
            float2 f1 = unpack2(acc[r][1]);
            float2 f2 = unpack2(acc[r][2]);
            float2 f3 = unpack2(acc[r][3]);
            int row = mg4 + r;
            float4 vA = make_float4(f0.x + sB2[nbA],     f0.y + sB2[nbA + 1],
                                    f1.x + sB2[nbA + 2], f1.y + sB2[nbA + 3]);
            float4 vB = make_float4(f2.x + sB2[nbB],     f2.y + sB2[nbB + 1],
                                    f3.x + sB2[nbB + 2], f3.y + sB2[nbB + 3]);
            *reinterpret_cast<float4*>(sW + row * NHALF + nbA)        = vA;
            *reinterpret_cast<float4*>(sW + row * NHALF + (nbB ^ 16)) = vB;
        }
        __syncthreads();

        // ---- phase 3: contractions + atomic scatter ----
        // note: cols >= 256 are stored with u -> u^1 permutation (XOR-16 swizzle)
        if (role == 0) {
            #pragma unroll
            for (int r = 0; r < 2; ++r) {
                int task = t + r * THREADS;       // 1024 = 32 e * 32 outputs
                int e = task >> 5, o = task & 31;
                int v = o & 15, sel = o >> 4;     // sel0: y00 (a), sel1: y01 (xs, permuted)
                const float* w = sW + e * NHALF + (sel ? 256 + v : v);
                const float* x = sX + e * 64 + (sel ? 0 : 16);
                int xm = sel;                     // u^1 for swizzled half
                float y = 0.0f;
                #pragma unroll
                for (int u = 0; u < 16; ++u) y += x[u ^ xm] * w[u * 16];
                int dst = sDst[e];
                if (sel == 0) {
                    atomicAdd(&g_agg[dst * 64 + v], ALPHA * y);
                } else {
                    float ay = ALPHA * y;
                    atomicAdd(&g_agg[dst*64 + 16 + v*3 + 0], ay * sSH[e*4+1]);
                    atomicAdd(&g_agg[dst*64 + 16 + v*3 + 1], ay * sSH[e*4+2]);
                    atomicAdd(&g_agg[dst*64 + 16 + v*3 + 2], ay * sSH[e*4+3]);
                }
            }
        } else {
            #pragma unroll
            for (int r = 0; r < 4; ++r) {
                int task = t + r * THREADS;       // 2048 = 32 e * 64 outputs
                int e = task >> 6, o = task & 63;
                int dst = sDst[e];
                if (o < 16) {                     // y11 (b, permuted cols)
                    int v = o;
                    const float* x = sX + e * 64;
                    const float* w = sW + e * NHALF + 256 + v;
                    float y = 0.0f;
                    #pragma unroll
                    for (int u = 0; u < 16; ++u) y += x[u ^ 1] * w[u * 16];
                    atomicAdd(&g_agg[dst * 64 + v], ALPHA * INV3 * y);
                } else {                          // y10_i (shs*xv_i)
                    int oo = o - 16;
                    int i = oo >> 4, v = oo & 15;
                    const float* x = sX + e * 64 + 16 + i * 16;
                    const float* w = sW + e * NHALF + v;
                    float y = 0.0f;
                    #pragma unroll
                    for (int u = 0; u < 16; ++u) y += x[u] * w[u * 16];
                    atomicAdd(&g_agg[dst * 64 + 16 + v * 3 + i], ALPHA * y);
                }
            }
        }
        __syncthreads();
    }
}

__global__ __launch_bounds__(256)
void node_kernel(const float* __restrict__ nf,
                 const float* __restrict__ lw0,
                 const float* __restrict__ lw1,
                 float* __restrict__ out)
{
    __shared__ float sw0[256], sw1[256];
    int t = threadIdx.x;
    sw0[t] = lw0[t];
    sw1[t] = lw1[t];
    __syncthreads();

    int node = blockIdx.x * 16 + (t >> 4);
    int v = t & 15;
    const float* a = g_agg + node * 64;

    float ts = 0.0f, t0 = 0.0f, t1 = 0.0f, t2 = 0.0f;
    #pragma unroll
    for (int u = 0; u < 16; ++u) {
        float c0 = sw0[u * 16 + v];
        float c1 = sw1[u * 16 + v];
        ts += a[u] * c0;
        t0 += a[16 + u * 3 + 0] * c1;
        t1 += a[16 + u * 3 + 1] * c1;
        t2 += a[16 + u * 3 + 2] * c1;
    }
    const float S = 0.25f, EPS = 1e-8f;
    ts *= S; t0 *= S; t1 *= S; t2 *= S;

    float ns = fabsf(ts);
    float gs = ns / ((ns + EPS) * (1.0f + __expf(-ns)));
    float nv = sqrtf(t0 * t0 + t1 * t1 + t2 * t2);
    float gv = nv / ((nv + EPS) * (1.0f + __expf(-nv)));

    int base = node * 64;
    out[base + v] = nf[base + v] + ts * gs;
    out[base + 16 + v * 3 + 0] = nf[base + 16 + v * 3 + 0] + t0 * gv;
    out[base + 16 + v * 3 + 1] = nf[base + 16 + v * 3 + 1] + t1 * gv;
    out[base + 16 + v * 3 + 2] = nf[base + 16 + v * 3 + 2] + t2 * gv;
}

extern "C" void kernel_launch(void* const* d_in, const int* in_sizes, int n_in,
                              void* d_out, int out_size)
{
    const float* nf   = (const float*)d_in[0];
    const float* esh  = (const float*)d_in[1];
    const float* emb  = (const float*)d_in[2];
    const float* w1   = (const float*)d_in[3];
    const float* b1   = (const float*)d_in[4];
    const float* w2   = (const float*)d_in[5];
    const float* b2   = (const float*)d_in[6];
    const float* lw0  = (const float*)d_in[7];
    const float* lw1  = (const float*)d_in[8];
    const int*   eidx = (const int*)d_in[9];
    float* out = (float*)d_out;

    cudaFuncSetAttribute(edge_kernel, cudaFuncAttributeMaxDynamicSharedMemorySize, SMEM_BYTES);

    zero_kernel<<<625, 1024>>>();
    edge_kernel<<<148, THREADS, SMEM_BYTES>>>(nf, esh, emb, w1, b1, w2, b2, eidx);
    node_kernel<<<625, 256>>>(nf, lw0, lw1, out);
}